// round 3
// baseline (speedup 1.0000x reference)
#include <cuda_runtime.h>
#include <cuda_bf16.h>

#define THREADS 256

// One block per graph. batch is sorted ascending, so graph g's nodes occupy a
// contiguous range found by binary search. Block-reduce cols 11 & 24, then
// thread 0 runs the tiny MLP and writes out[g]. Single launch, no atomics.
__global__ void __launch_bounds__(THREADS)
fused_kernel(const float* __restrict__ nf,
             const int*   __restrict__ batch,
             const float* __restrict__ W1,   // [32,2]
             const float* __restrict__ b1,   // [32]
             const float* __restrict__ W2,   // [1,32]
             const float* __restrict__ b2,   // [1]
             float* __restrict__ out,
             int N) {
    const int g = blockIdx.x;
    __shared__ int s_bounds[2];
    __shared__ float s_red[2][THREADS / 32];

    // lower_bound(batch, g) and lower_bound(batch, g+1), one per thread 0/1.
    if (threadIdx.x < 2) {
        int key = g + threadIdx.x;   // find first index with batch[i] >= key
        int lo = 0, hi = N;
        while (lo < hi) {
            int mid = (lo + hi) >> 1;
            if (batch[mid] < key) lo = mid + 1; else hi = mid;
        }
        s_bounds[threadIdx.x] = lo;
    }
    __syncthreads();
    const int start = s_bounds[0];
    const int end   = s_bounds[1];
    const int count = end - start;

    // Strided sum over this graph's rows: cols 11 (modifier) and 24 (owner).
    float v0 = 0.0f, v1 = 0.0f;
    for (int i = start + threadIdx.x; i < end; i += THREADS) {
        const float* row = nf + (size_t)i * 128;
        v0 += __ldg(row + 11);
        v1 += __ldg(row + 24);
    }

    // Warp reduce
    #pragma unroll
    for (int off = 16; off > 0; off >>= 1) {
        v0 += __shfl_down_sync(0xffffffffu, v0, off);
        v1 += __shfl_down_sync(0xffffffffu, v1, off);
    }
    const int lane = threadIdx.x & 31;
    const int wid  = threadIdx.x >> 5;
    if (lane == 0) { s_red[0][wid] = v0; s_red[1][wid] = v1; }
    __syncthreads();

    if (threadIdx.x == 0) {
        float s0 = 0.0f, s1 = 0.0f;
        #pragma unroll
        for (int w = 0; w < THREADS / 32; w++) { s0 += s_red[0][w]; s1 += s_red[1][w]; }

        float denom = fmaxf((float)count, 1.0f);
        float a0 = 1.0f - s0 / denom;
        float a1 = 1.0f - s1 / denom;

        float acc = __ldg(b2);
        #pragma unroll
        for (int j = 0; j < 32; j++) {
            float h = fmaf(a0, __ldg(W1 + j * 2 + 0),
                      fmaf(a1, __ldg(W1 + j * 2 + 1), __ldg(b1 + j)));
            h = fmaxf(h, 0.0f);
            acc = fmaf(h, __ldg(W2 + j), acc);
        }
        float score = 1.0f / (1.0f + __expf(-acc));
        out[g] = (count > 0) ? score : 0.0f;
    }
}

extern "C" void kernel_launch(void* const* d_in, const int* in_sizes, int n_in,
                              void* d_out, int out_size) {
    // metadata order: node_features, batch, graph_embedding(unused), W1, b1, W2, b2
    const float* nf    = (const float*)d_in[0];
    const int*   batch = (const int*)d_in[1];
    const float* W1    = (const float*)d_in[3];
    const float* b1    = (const float*)d_in[4];
    const float* W2    = (const float*)d_in[5];
    const float* b2    = (const float*)d_in[6];
    float*       out   = (float*)d_out;

    int N = in_sizes[1];   // number of nodes
    int G = out_size;      // number of graphs

    fused_kernel<<<G, THREADS>>>(nf, batch, W1, b1, W2, b2, out, N);
}